// round 15
// baseline (speedup 1.0000x reference)
#include <cuda_runtime.h>
#include <cuda_fp16.h>
#include <cstdint>
#include <math.h>

#define BATCH 2
#define SEQ   2048
#define DMODEL 1024
#define NHEAD 16
#define HDIM  64
#define THD   (NHEAD * HDIM)
#define MROWS (BATCH * SEQ)
#define QK_COLS (2 * THD)
#define GN_EPS 1e-5f
#define QSCALE_F 0.18033688f   // 0.125 * log2(e)
#define ONES16 0x3C003C00u     // half2(1.0, 1.0)

// ---------------- scratch ----------------
__device__ __half g_Qh[MROWS * QK_COLS];
__device__ __half g_Kh[MROWS * QK_COLS];
__device__ __half g_V16[MROWS * THD];
__device__ float g_cosT[SEQ * 32];
__device__ float g_sinT[SEQ * 32];
__device__ __half g_xh[MROWS * DMODEL],  g_xl[MROWS * DMODEL];
__device__ __half g_Wq16[DMODEL * QK_COLS];
__device__ __half g_Wk16[DMODEL * QK_COLS];
__device__ __half g_Wv16[DMODEL * THD];
__device__ __half g_Wo16[THD * DMODEL];
__device__ __half g_Ah[MROWS * THD], g_Al[MROWS * THD];

// ---------------- helpers ----------------
__device__ __forceinline__ void ldsm4(unsigned &r0, unsigned &r1, unsigned &r2, unsigned &r3, unsigned a) {
    asm volatile("ldmatrix.sync.aligned.m8n8.x4.shared.b16 {%0,%1,%2,%3}, [%4];"
        : "=r"(r0), "=r"(r1), "=r"(r2), "=r"(r3) : "r"(a));
}
__device__ __forceinline__ void ldsmT4(unsigned &r0, unsigned &r1, unsigned &r2, unsigned &r3, unsigned a) {
    asm volatile("ldmatrix.sync.aligned.m8n8.x4.trans.shared.b16 {%0,%1,%2,%3}, [%4];"
        : "=r"(r0), "=r"(r1), "=r"(r2), "=r"(r3) : "r"(a));
}
__device__ __forceinline__ void mma16h(float* c, const unsigned* a, unsigned b0, unsigned b1) {
    asm volatile("mma.sync.aligned.m16n8k16.row.col.f32.f16.f16.f32 "
        "{%0,%1,%2,%3},{%4,%5,%6,%7},{%8,%9},{%0,%1,%2,%3};"
        : "+f"(c[0]), "+f"(c[1]), "+f"(c[2]), "+f"(c[3])
        : "r"(a[0]), "r"(a[1]), "r"(a[2]), "r"(a[3]), "r"(b0), "r"(b1));
}
__device__ __forceinline__ void cp16(unsigned s, const void* g) {
    asm volatile("cp.async.cg.shared.global [%0], [%1], 16;" :: "r"(s), "l"(g));
}
__device__ __forceinline__ void cpcommit() { asm volatile("cp.async.commit_group;"); }
__device__ __forceinline__ unsigned h2exp2(unsigned x) {
    unsigned r;
    asm("ex2.approx.f16x2 %0, %1;" : "=r"(r) : "r"(x));
    return r;
}
__device__ __forceinline__ unsigned packsub(float a, float b, float m) {
    __half2 h = __floats2half2_rn(a - m, b - m);
    return *(unsigned*)&h;
}

// ---------------- fused input-split + weight-convert ----------------
__global__ void prep_kernel(const float* __restrict__ x,
                            const float* __restrict__ Wq, const float* __restrict__ Wk,
                            const float* __restrict__ Wv, const float* __restrict__ Wo,
                            __half* __restrict__ xh, __half* __restrict__ xl,
                            __half* __restrict__ q16, __half* __restrict__ k16,
                            __half* __restrict__ v16, __half* __restrict__ o16) {
    int which = blockIdx.y;
    int i = blockIdx.x * blockDim.x + threadIdx.x;
    if (which == 0) {
        if (i >= MROWS * DMODEL) return;
        float v = x[i];
        __half hv = __float2half_rn(v);
        xh[i] = hv;
        xl[i] = __float2half_rn(v - __half2float(hv));
        return;
    }
    const float* s;
    __half* d;
    int n;
    if (which == 1)      { s = Wq; d = q16; n = DMODEL * QK_COLS; }
    else if (which == 2) { s = Wk; d = k16; n = DMODEL * QK_COLS; }
    else if (which == 3) { s = Wv; d = v16; n = DMODEL * THD; }
    else                 { s = Wo; d = o16; n = THD * DMODEL; }
    if (i < n) d[i] = __float2half_rn(s[i]);
}

__global__ void rope_tables_kernel(float* __restrict__ cosT, float* __restrict__ sinT) {
    int i = blockIdx.x * blockDim.x + threadIdx.x;
    if (i >= SEQ * 32) return;
    int t = i >> 5, j = i & 31;
    double invf = pow(10000.0, -(double)(2 * j) / 64.0);
    float f = (float)t * (float)invf;
    cosT[i] = (float)cos((double)f);
    sinT[i] = (float)sin((double)f);
}

// ---------------- GEMM tile geometry (BK=64, 2-stage) ----------------
#define GA_ST 72
#define GB_ST 136
#define O_AH 0
#define O_AL (128 * GA_ST)
#define O_B  (2 * 128 * GA_ST)
#define STG_EL (O_B + 64 * GB_ST)
#define GEMM_SMEM (2 * STG_EL * 2)

// ---------------- merged QKV projection GEMM (flattened grid.x: 16Q+16K+8V) ----------------
__global__ __launch_bounds__(256) void gemm_qkv_kernel(
    const __half* __restrict__ Ah, const __half* __restrict__ Al,
    const __half* __restrict__ Wq, const __half* __restrict__ Wk, const __half* __restrict__ Wv,
    __half* __restrict__ Qo, __half* __restrict__ Ko, __half* __restrict__ Vo,
    const float* __restrict__ cosT, const float* __restrict__ sinT)
{
    int bx = blockIdx.x;
    int z, bxl;
    if (bx < 16)      { z = 0; bxl = bx; }
    else if (bx < 32) { z = 1; bxl = bx - 16; }
    else              { z = 2; bxl = bx - 32; }
    const int N = (z == 2) ? THD : QK_COLS;
    const int K = DMODEL;
    const __half* B = (z == 0) ? Wq : (z == 1) ? Wk : Wv;
    __half* C = (z == 0) ? Qo : (z == 1) ? Ko : Vo;
    const float oscale = (z == 0) ? QSCALE_F : 1.0f;

    extern __shared__ __half smb[];
    const unsigned smB = (unsigned)__cvta_generic_to_shared(smb);
    const int tid = threadIdx.x, wid = tid >> 5, lane = tid & 31;
    const int wm = wid & 3, wn = wid >> 2;
    const int g = lane >> 2, t = lane & 3;
    const int bm0 = blockIdx.y * 128, bn0 = bxl * 128;

    float acc[2][8][4];
#pragma unroll
    for (int i = 0; i < 2; i++)
#pragma unroll
        for (int j = 0; j < 8; j++)
#pragma unroll
            for (int c = 0; c < 4; c++) acc[i][j][c] = 0.f;

    auto load_stage = [&](int kt, int stg) {
        const int k0 = kt * 64;
        const unsigned sb = smB + stg * (STG_EL * 2);
#pragma unroll
        for (int q = 0; q < 8; q++) {
            int fi = tid + q * 256;
            int u = fi >> 10, idx = fi & 1023;
            int r = idx >> 3, c = (idx & 7) * 8;
            cp16(sb + ((u ? O_AL : O_AH) + r * GA_ST + c) * 2,
                 (u ? Al : Ah) + (size_t)(bm0 + r) * K + k0 + c);
        }
#pragma unroll
        for (int q = 0; q < 4; q++) {
            int fi = tid + q * 256;
            int r = fi >> 4, c = (fi & 15) * 8;
            cp16(sb + (O_B + r * GB_ST + c) * 2,
                 B + (size_t)(k0 + r) * N + bn0 + c);
        }
        cpcommit();
    };
    const int NT = K >> 6;
    load_stage(0, 0);

    const unsigned aoff = ((lane & 15) * GA_ST + (lane >> 4) * 8) * 2;
    const unsigned boff = (((((lane >> 3) & 1) * 8) + (lane & 7)) * GB_ST + (lane >> 4) * 8) * 2;

    for (int kt = 0; kt < NT; kt++) {
        asm volatile("cp.async.wait_group 0;");
        __syncthreads();
        if (kt + 1 < NT) load_stage(kt + 1, (kt + 1) & 1);

        const unsigned sb = smB + (kt & 1) * (STG_EL * 2);
#pragma unroll
        for (int ks = 0; ks < 4; ks++) {
            unsigned AH[2][4], AL[2][4];
#pragma unroll
            for (int mf = 0; mf < 2; mf++) {
                unsigned a = sb + (wm * 32 + mf * 16) * GA_ST * 2 + aoff + ks * 32;
                ldsm4(AH[mf][0], AH[mf][1], AH[mf][2], AH[mf][3], a + O_AH * 2);
                ldsm4(AL[mf][0], AL[mf][1], AL[mf][2], AL[mf][3], a + O_AL * 2);
            }
#pragma unroll
            for (int np = 0; np < 4; np++) {
                unsigned bofs = sb + boff + ks * 16 * GB_ST * 2 + O_B * 2 + (wn * 64 + np * 16) * 2;
                unsigned TB[4];
                ldsmT4(TB[0], TB[1], TB[2], TB[3], bofs);
#pragma unroll
                for (int hh = 0; hh < 2; hh++) {
                    int nf = np * 2 + hh;
#pragma unroll
                    for (int mf = 0; mf < 2; mf++) {
                        mma16h(acc[mf][nf], AH[mf], TB[2 * hh], TB[2 * hh + 1]);
                        mma16h(acc[mf][nf], AL[mf], TB[2 * hh], TB[2 * hh + 1]);
                    }
                }
            }
        }
    }

#pragma unroll
    for (int mf = 0; mf < 2; mf++) {
#pragma unroll
        for (int half = 0; half < 2; half++) {
            size_t row = (size_t)(bm0 + wm * 32 + mf * 16 + g + 8 * half);
            if (z < 2) {
                int s = (int)(row & (SEQ - 1));
#pragma unroll
                for (int nf = 0; nf < 4; nf++) {
                    int d = nf * 8 + 2 * t;
                    float2 cc = *(const float2*)&cosT[s * 32 + d];
                    float2 ss = *(const float2*)&sinT[s * 32 + d];
                    float lo0 = acc[mf][nf][2 * half], lo1 = acc[mf][nf][2 * half + 1];
                    float hi0 = acc[mf][nf + 4][2 * half], hi1 = acc[mf][nf + 4][2 * half + 1];
                    int c0 = bn0 + wn * 64 + d;
                    *(__half2*)&C[row * N + c0] = __floats2half2_rn(
                        (lo0 * cc.x - hi0 * ss.x) * oscale, (lo1 * cc.y - hi1 * ss.y) * oscale);
                    *(__half2*)&C[row * N + c0 + 32] = __floats2half2_rn(
                        (hi0 * cc.x + lo0 * ss.x) * oscale, (hi1 * cc.y + lo1 * ss.y) * oscale);
                }
            } else {
#pragma unroll
                for (int nf = 0; nf < 8; nf++) {
                    int c = bn0 + wn * 64 + nf * 8 + 2 * t;
                    *(__half2*)&C[row * N + c] =
                        __floats2half2_rn(acc[mf][nf][2 * half], acc[mf][nf][2 * half + 1]);
                }
            }
        }
    }
}

// ---------------- Wo GEMM (f32 out) ----------------
__global__ __launch_bounds__(256) void gemm_o_kernel(
    const __half* __restrict__ Ah, const __half* __restrict__ Al,
    const __half* __restrict__ B, float* __restrict__ C, int M, int N, int K)
{
    extern __shared__ __half smb[];
    const unsigned smB = (unsigned)__cvta_generic_to_shared(smb);
    const int tid = threadIdx.x, wid = tid >> 5, lane = tid & 31;
    const int wm = wid & 3, wn = wid >> 2;
    const int g = lane >> 2, t = lane & 3;
    const int bm0 = blockIdx.y * 128, bn0 = blockIdx.x * 128;

    float acc[2][8][4];
#pragma unroll
    for (int i = 0; i < 2; i++)
#pragma unroll
        for (int j = 0; j < 8; j++)
#pragma unroll
            for (int c = 0; c < 4; c++) acc[i][j][c] = 0.f;

    auto load_stage = [&](int kt, int stg) {
        const int k0 = kt * 64;
        const unsigned sb = smB + stg * (STG_EL * 2);
#pragma unroll
        for (int q = 0; q < 8; q++) {
            int fi = tid + q * 256;
            int u = fi >> 10, idx = fi & 1023;
            int r = idx >> 3, c = (idx & 7) * 8;
            cp16(sb + ((u ? O_AL : O_AH) + r * GA_ST + c) * 2,
                 (u ? Al : Ah) + (size_t)(bm0 + r) * K + k0 + c);
        }
#pragma unroll
        for (int q = 0; q < 4; q++) {
            int fi = tid + q * 256;
            int r = fi >> 4, c = (fi & 15) * 8;
            cp16(sb + (O_B + r * GB_ST + c) * 2,
                 B + (size_t)(k0 + r) * N + bn0 + c);
        }
        cpcommit();
    };
    const int NT = K >> 6;
    load_stage(0, 0);

    const unsigned aoff = ((lane & 15) * GA_ST + (lane >> 4) * 8) * 2;
    const unsigned boff = (((((lane >> 3) & 1) * 8) + (lane & 7)) * GB_ST + (lane >> 4) * 8) * 2;

    for (int kt = 0; kt < NT; kt++) {
        asm volatile("cp.async.wait_group 0;");
        __syncthreads();
        if (kt + 1 < NT) load_stage(kt + 1, (kt + 1) & 1);

        const unsigned sb = smB + (kt & 1) * (STG_EL * 2);
#pragma unroll
        for (int ks = 0; ks < 4; ks++) {
            unsigned AH[2][4], AL[2][4];
#pragma unroll
            for (int mf = 0; mf < 2; mf++) {
                unsigned a = sb + (wm * 32 + mf * 16) * GA_ST * 2 + aoff + ks * 32;
                ldsm4(AH[mf][0], AH[mf][1], AH[mf][2], AH[mf][3], a + O_AH * 2);
                ldsm4(AL[mf][0], AL[mf][1], AL[mf][2], AL[mf][3], a + O_AL * 2);
            }
#pragma unroll
            for (int np = 0; np < 4; np++) {
                unsigned bofs = sb + boff + ks * 16 * GB_ST * 2 + O_B * 2 + (wn * 64 + np * 16) * 2;
                unsigned TB[4];
                ldsmT4(TB[0], TB[1], TB[2], TB[3], bofs);
#pragma unroll
                for (int hh = 0; hh < 2; hh++) {
                    int nf = np * 2 + hh;
#pragma unroll
                    for (int mf = 0; mf < 2; mf++) {
                        mma16h(acc[mf][nf], AH[mf], TB[2 * hh], TB[2 * hh + 1]);
                        mma16h(acc[mf][nf], AL[mf], TB[2 * hh], TB[2 * hh + 1]);
                    }
                }
            }
        }
    }

#pragma unroll
    for (int mf = 0; mf < 2; mf++) {
        size_t r0 = (size_t)(bm0 + wm * 32 + mf * 16 + g);
#pragma unroll
        for (int nf = 0; nf < 8; nf++) {
            int c = bn0 + wn * 64 + nf * 8 + 2 * t;
            *(float2*)&C[r0 * N + c]       = make_float2(acc[mf][nf][0], acc[mf][nf][1]);
            *(float2*)&C[(r0 + 8) * N + c] = make_float2(acc[mf][nf][2], acc[mf][nf][3]);
        }
    }
}

// ---------------- fp16 differential flash attention v8 ----------------
// one sync per k-tile; half2-packed max shuffles; exp2/f16x2 softmax; ones-MMA lsum.
#define HROW 144
#define QTILE 9216
#define ST_STRIDE 27648
#define ATT_SMEM (4 * QTILE + 2 * ST_STRIDE)   // 92160
#define NKT (SEQ / 64)

__global__ __launch_bounds__(256) void attn_v8_kernel(
    const __half* __restrict__ Q, const __half* __restrict__ K, const __half* __restrict__ V,
    const float* __restrict__ lq1, const float* __restrict__ lk1,
    const float* __restrict__ lq2, const float* __restrict__ lk2,
    const float* __restrict__ lam_init_p,
    const float* __restrict__ gnw, const float* __restrict__ gnb,
    __half* __restrict__ OutH, __half* __restrict__ OutL)
{
    extern __shared__ char smv[];
    const unsigned smBase = (unsigned)__cvta_generic_to_shared(smv);
    const int tid = threadIdx.x, wid = tid >> 5, lane = tid & 31;
    const int br = wid >> 2, mblk = wid & 3;
    const int g = lane >> 2, t = lane & 3;
    const int bh = blockIdx.y, b = bh >> 4, h = bh & 15;
    const int q0 = blockIdx.x * 128;
    const int rowg0 = b * SEQ;
    const int c1base = h * HDIM;

#pragma unroll
    for (int q = 0; q < 4; q++) {
        int fi = tid + q * 256;
        int r = fi >> 3, c = fi & 7;
        const __half* gq = &Q[(size_t)(rowg0 + q0 + r) * QK_COLS + c1base + c * 8];
        cp16(smBase + r * HROW + c * 16, gq);
        cp16(smBase + 2 * QTILE + r * HROW + c * 16, gq + THD);
    }
    auto load_stage = [&](int kt, int stg) {
        const int k0 = kt * 64;
        const unsigned base = smBase + 4 * QTILE + stg * ST_STRIDE;
#pragma unroll
        for (int q = 0; q < 2; q++) {
            int fi = tid + q * 256;
            int r = fi >> 3, c = fi & 7;
            const __half* gk = &K[(size_t)(rowg0 + k0 + r) * QK_COLS + c1base + c * 8];
            cp16(base + r * HROW + c * 16, gk);
            cp16(base + QTILE + r * HROW + c * 16, gk + THD);
            cp16(base + 2 * QTILE + r * HROW + c * 16,
                 &V[(size_t)(rowg0 + k0 + r) * THD + c1base + c * 8]);
        }
        cpcommit();
    };
    load_stage(0, 0);

    const unsigned aoff = (lane & 15) * HROW + (lane >> 4) * 16;
    const unsigned boff = ((lane & 7) + ((lane >> 4) << 3)) * HROW + ((lane >> 3) & 1) * 16;
    const unsigned boffT = (((lane & 7) + (((lane >> 3) & 1) << 3)) * HROW) + (lane >> 4) * 16;
    const unsigned aQw = smBase + br * (2 * QTILE) + mblk * 32 * HROW + aoff;

    float O[2][8][4];
#pragma unroll
    for (int mf = 0; mf < 2; mf++)
#pragma unroll
        for (int df = 0; df < 8; df++)
#pragma unroll
            for (int c = 0; c < 4; c++) O[mf][df][c] = 0.f;
    float mmx[2][2] = {{-1e30f, -1e30f}, {-1e30f, -1e30f}};
    float lsA[2][4] = {{0.f, 0.f, 0.f, 0.f}, {0.f, 0.f, 0.f, 0.f}};

    for (int kt = 0; kt < NKT; kt++) {
        asm volatile("cp.async.wait_group 0;");
        __syncthreads();
        if (kt + 1 < NKT) load_stage(kt + 1, (kt + 1) & 1);

        const unsigned stb = smBase + 4 * QTILE + (kt & 1) * ST_STRIDE;
        const unsigned kB = stb + br * QTILE + boff;
        const unsigned vB = stb + 2 * QTILE + boffT;

        float S[2][8][4];
#pragma unroll
        for (int mf = 0; mf < 2; mf++)
#pragma unroll
            for (int nf = 0; nf < 8; nf++)
#pragma unroll
                for (int c = 0; c < 4; c++) S[mf][nf][c] = 0.f;

#pragma unroll
        for (int p = 0; p < 4; p++) {
            unsigned A[2][4];
#pragma unroll
            for (int mf = 0; mf < 2; mf++)
                ldsm4(A[mf][0], A[mf][1], A[mf][2], A[mf][3],
                      aQw + mf * 16 * HROW + p * 32);
#pragma unroll
            for (int nb = 0; nb < 4; nb++) {
                unsigned Bf[4];
                ldsm4(Bf[0], Bf[1], Bf[2], Bf[3], kB + nb * 16 * HROW + p * 32);
#pragma unroll
                for (int mf = 0; mf < 2; mf++) {
                    mma16h(S[mf][2 * nb],     A[mf], Bf[0], Bf[1]);
                    mma16h(S[mf][2 * nb + 1], A[mf], Bf[2], Bf[3]);
                }
            }
        }

        // exp2-domain softmax; max reduced as packed half2 (precision of m is immaterial)
        unsigned P2[2][8][2];
#pragma unroll
        for (int mf = 0; mf < 2; mf++) {
            float mx0 = -1e30f, mx1 = -1e30f;
#pragma unroll
            for (int nf = 0; nf < 8; nf++) {
                mx0 = fmaxf(mx0, fmaxf(S[mf][nf][0], S[mf][nf][1]));
                mx1 = fmaxf(mx1, fmaxf(S[mf][nf][2], S[mf][nf][3]));
            }
            __half2 mp = __floats2half2_rn(mx0, mx1);
            unsigned mu = *(unsigned*)&mp;
            unsigned o1 = __shfl_xor_sync(0xffffffffu, mu, 1);
            mp = __hmax2(mp, *(__half2*)&o1);
            mu = *(unsigned*)&mp;
            o1 = __shfl_xor_sync(0xffffffffu, mu, 2);
            mp = __hmax2(mp, *(__half2*)&o1);
            mx0 = __low2float(mp);
            mx1 = __high2float(mp);
            float mn0 = fmaxf(mmx[mf][0], mx0);
            float mn1 = fmaxf(mmx[mf][1], mx1);
            float c0 = exp2f(mmx[mf][0] - mn0);
            float c1 = exp2f(mmx[mf][1] - mn1);
            mmx[mf][0] = mn0; mmx[mf][1] = mn1;
            lsA[mf][0] *= c0; lsA[mf][1] *= c0;
            lsA[mf][2] *= c1; lsA[mf][3] *= c1;
#pragma unroll
            for (int nf = 0; nf < 8; nf++) {
                P2[mf][nf][0] = h2exp2(packsub(S[mf][nf][0], S[mf][nf][1], mn0));
                P2[mf][nf][1] = h2exp2(packsub(S[mf][nf][2], S[mf][nf][3], mn1));
            }
#pragma unroll
            for (int df = 0; df < 8; df++) {
                O[mf][df][0] *= c0; O[mf][df][1] *= c0;
                O[mf][df][2] *= c1; O[mf][df][3] *= c1;
            }
        }

#pragma unroll
        for (int p = 0; p < 4; p++) {
            unsigned PA[2][4];
#pragma unroll
            for (int mf = 0; mf < 2; mf++) {
                PA[mf][0] = P2[mf][2 * p][0];
                PA[mf][1] = P2[mf][2 * p][1];
                PA[mf][2] = P2[mf][2 * p + 1][0];
                PA[mf][3] = P2[mf][2 * p + 1][1];
                mma16h(lsA[mf], PA[mf], ONES16, ONES16);
            }
#pragma unroll
            for (int nb = 0; nb < 4; nb++) {
                unsigned Bf[4];
                ldsmT4(Bf[0], Bf[1], Bf[2], Bf[3], vB + p * 16 * HROW + nb * 32);
#pragma unroll
                for (int mf = 0; mf < 2; mf++) {
                    mma16h(O[mf][2 * nb],     PA[mf], Bf[0], Bf[1]);
                    mma16h(O[mf][2 * nb + 1], PA[mf], Bf[2], Bf[3]);
                }
            }
        }
    }

    const float lam_init = lam_init_p[0];
    const float lam = __expf(lq1[h] * lk1[h]) - __expf(lq2[h] * lk2[h]) + lam_init;
    const float osc = 1.0f - lam_init;
    float* Ex = (float*)(smv + 4 * QTILE);

    __syncthreads();   // all warps out of mainloop before Ex overwrites stage area
    if (br == 1) {
#pragma unroll
        for (int mf = 0; mf < 2; mf++) {
            float inv0 = lam / lsA[mf][0];
            float inv1 = lam / lsA[mf][2];
            int row0 = mblk * 32 + mf * 16 + g;
#pragma unroll
            for (int df = 0; df < 8; df++) {
                int col = df * 8 + 2 * t;
                *(float2*)&Ex[row0 * 68 + col] = make_float2(O[mf][df][0] * inv0, O[mf][df][1] * inv0);
                *(float2*)&Ex[(row0 + 8) * 68 + col] = make_float2(O[mf][df][2] * inv1, O[mf][df][3] * inv1);
            }
        }
    }
    __syncthreads();
    if (br == 0) {
#pragma unroll
        for (int mf = 0; mf < 2; mf++) {
#pragma unroll
            for (int half = 0; half < 2; half++) {
                float inv1 = 1.0f / lsA[mf][2 * half];
                int lrow = mblk * 32 + mf * 16 + g + 8 * half;
                float v[16];
                float s = 0.f, sq = 0.f;
#pragma unroll
                for (int df = 0; df < 8; df++) {
                    float2 e = *(float2*)&Ex[lrow * 68 + df * 8 + 2 * t];
                    float a0 = O[mf][df][half * 2 + 0] * inv1 - e.x;
                    float a1 = O[mf][df][half * 2 + 1] * inv1 - e.y;
                    v[2 * df] = a0; v[2 * df + 1] = a1;
                    s += a0 + a1; sq += a0 * a0 + a1 * a1;
                }
                s  += __shfl_xor_sync(0xffffffffu, s, 1);
                s  += __shfl_xor_sync(0xffffffffu, s, 2);
                sq += __shfl_xor_sync(0xffffffffu, sq, 1);
                sq += __shfl_xor_sync(0xffffffffu, sq, 2);
                float mean = s * (1.0f / 64.0f);
                float var = sq * (1.0f / 64.0f) - mean * mean;
                float istd = rsqrtf(var + GN_EPS);
                size_t grow = (size_t)(rowg0 + q0 + lrow);
#pragma unroll
                for (int df = 0; df < 8; df++) {
                    int col = h * HDIM + df * 8 + 2 * t;
                    float2 gw = *(const float2*)&gnw[col];
                    float2 gb = *(const float2*)&gnb[col];
                    float o0 = ((v[2 * df]     - mean) * istd * gw.x + gb.x) * osc;
                    float o1 = ((v[2 * df + 1] - mean) * istd * gw.y + gb.y) * osc;
                    __half h0 = __float2half_rn(o0);
                    __half h1 = __float2half_rn(o1);
                    __half2 ph; ph.x = h0; ph.y = h1;
                    __half2 pl;
                    pl.x = __float2half_rn(o0 - __half2float(h0));
                    pl.y = __float2half_rn(o1 - __half2float(h1));
                    *(__half2*)&OutH[grow * THD + col] = ph;
                    *(__half2*)&OutL[grow * THD + col] = pl;
                }
            }
        }
    }
}

// ---------------- kernel_launch ----------------
extern "C" void kernel_launch(void* const* d_in, const int* in_sizes, int n_in,
                              void* d_out, int out_size)
{
    const float* x   = (const float*)d_in[0];
    const float* Wq  = (const float*)d_in[1];
    const float* Wk  = (const float*)d_in[2];
    const float* Wv  = (const float*)d_in[3];
    const float* Wo  = (const float*)d_in[4];
    const float* lq1 = (const float*)d_in[5];
    const float* lk1 = (const float*)d_in[6];
    const float* lq2 = (const float*)d_in[7];
    const float* lk2 = (const float*)d_in[8];
    const float* lam = (const float*)d_in[9];
    const float* gnw = (const float*)d_in[10];
    const float* gnb = (const float*)d_in[11];
    float* out = (float*)d_out;

    float *cosT, *sinT;
    __half *Qh, *Kh, *V16, *xh, *xl, *Wq16, *Wk16, *Wv16, *Wo16, *Ah, *Al;
    cudaGetSymbolAddress((void**)&Qh, g_Qh);
    cudaGetSymbolAddress((void**)&Kh, g_Kh);
    cudaGetSymbolAddress((void**)&V16, g_V16);
    cudaGetSymbolAddress((void**)&cosT, g_cosT);
    cudaGetSymbolAddress((void**)&sinT, g_sinT);
    cudaGetSymbolAddress((void**)&xh, g_xh);
    cudaGetSymbolAddress((void**)&xl, g_xl);
    cudaGetSymbolAddress((void**)&Wq16, g_Wq16);
    cudaGetSymbolAddress((void**)&Wk16, g_Wk16);
    cudaGetSymbolAddress((void**)&Wv16, g_Wv16);
    cudaGetSymbolAddress((void**)&Wo16, g_Wo16);
    cudaGetSymbolAddress((void**)&Ah, g_Ah);
    cudaGetSymbolAddress((void**)&Al, g_Al);

    cudaFuncSetAttribute(attn_v8_kernel, cudaFuncAttributeMaxDynamicSharedMemorySize, ATT_SMEM);
    cudaFuncSetAttribute(gemm_qkv_kernel, cudaFuncAttributeMaxDynamicSharedMemorySize, GEMM_SMEM);
    cudaFuncSetAttribute(gemm_o_kernel, cudaFuncAttributeMaxDynamicSharedMemorySize, GEMM_SMEM);

    rope_tables_kernel<<<(SEQ * 32 + 255) / 256, 256>>>(cosT, sinT);
    prep_kernel<<<dim3((MROWS * DMODEL + 255) / 256, 5), 256>>>(
        x, Wq, Wk, Wv, Wo, xh, xl, Wq16, Wk16, Wv16, Wo16);

    gemm_qkv_kernel<<<dim3(40, MROWS / 128), 256, GEMM_SMEM>>>(
        xh, xl, Wq16, Wk16, Wv16, Qh, Kh, V16, cosT, sinT);

    attn_v8_kernel<<<dim3(SEQ / 128, BATCH * NHEAD), 256, ATT_SMEM>>>(
        Qh, Kh, V16, lq1, lk1, lq2, lk2, lam, gnw, gnb, Ah, Al);

    gemm_o_kernel<<<dim3(DMODEL / 128, MROWS / 128), 256, GEMM_SMEM>>>(
        Ah, Al, Wo16, out, MROWS, DMODEL, THD);
}

// round 16
// speedup vs baseline: 1.0179x; 1.0179x over previous
#include <cuda_runtime.h>
#include <cuda_fp16.h>
#include <cstdint>
#include <math.h>

#define BATCH 2
#define SEQ   2048
#define DMODEL 1024
#define NHEAD 16
#define HDIM  64
#define THD   (NHEAD * HDIM)
#define MROWS (BATCH * SEQ)
#define QK_COLS (2 * THD)
#define GN_EPS 1e-5f
#define QSCALE_F 0.18033688f   // 0.125 * log2(e)
#define ONES16 0x3C003C00u     // half2(1.0, 1.0)

// ---------------- scratch ----------------
__device__ __half g_Qh[MROWS * QK_COLS];
__device__ __half g_Kh[MROWS * QK_COLS];
__device__ __half g_V16[MROWS * THD];
__device__ float g_cosT[SEQ * 32];
__device__ float g_sinT[SEQ * 32];
__device__ __half g_xh[MROWS * DMODEL],  g_xl[MROWS * DMODEL];
__device__ __half g_Wq16[DMODEL * QK_COLS];
__device__ __half g_Wk16[DMODEL * QK_COLS];
__device__ __half g_Wv16[DMODEL * THD];
__device__ __half g_Wo16[THD * DMODEL];
__device__ __half g_Ah[MROWS * THD], g_Al[MROWS * THD];

// ---------------- helpers ----------------
__device__ __forceinline__ void ldsm4(unsigned &r0, unsigned &r1, unsigned &r2, unsigned &r3, unsigned a) {
    asm volatile("ldmatrix.sync.aligned.m8n8.x4.shared.b16 {%0,%1,%2,%3}, [%4];"
        : "=r"(r0), "=r"(r1), "=r"(r2), "=r"(r3) : "r"(a));
}
__device__ __forceinline__ void ldsmT4(unsigned &r0, unsigned &r1, unsigned &r2, unsigned &r3, unsigned a) {
    asm volatile("ldmatrix.sync.aligned.m8n8.x4.trans.shared.b16 {%0,%1,%2,%3}, [%4];"
        : "=r"(r0), "=r"(r1), "=r"(r2), "=r"(r3) : "r"(a));
}
__device__ __forceinline__ void mma16h(float* c, const unsigned* a, unsigned b0, unsigned b1) {
    asm volatile("mma.sync.aligned.m16n8k16.row.col.f32.f16.f16.f32 "
        "{%0,%1,%2,%3},{%4,%5,%6,%7},{%8,%9},{%0,%1,%2,%3};"
        : "+f"(c[0]), "+f"(c[1]), "+f"(c[2]), "+f"(c[3])
        : "r"(a[0]), "r"(a[1]), "r"(a[2]), "r"(a[3]), "r"(b0), "r"(b1));
}
__device__ __forceinline__ void cp16(unsigned s, const void* g) {
    asm volatile("cp.async.cg.shared.global [%0], [%1], 16;" :: "r"(s), "l"(g));
}
__device__ __forceinline__ void cpcommit() { asm volatile("cp.async.commit_group;"); }
__device__ __forceinline__ unsigned h2exp2(unsigned x) {
    unsigned r;
    asm("ex2.approx.f16x2 %0, %1;" : "=r"(r) : "r"(x));
    return r;
}
__device__ __forceinline__ unsigned packsub(float a, float b, float m) {
    __half2 h = __floats2half2_rn(a - m, b - m);
    return *(unsigned*)&h;
}

// ---------------- fused input-split + weight-convert ----------------
__global__ void prep_kernel(const float* __restrict__ x,
                            const float* __restrict__ Wq, const float* __restrict__ Wk,
                            const float* __restrict__ Wv, const float* __restrict__ Wo,
                            __half* __restrict__ xh, __half* __restrict__ xl,
                            __half* __restrict__ q16, __half* __restrict__ k16,
                            __half* __restrict__ v16, __half* __restrict__ o16) {
    int which = blockIdx.y;
    int i = blockIdx.x * blockDim.x + threadIdx.x;
    if (which == 0) {
        if (i >= MROWS * DMODEL) return;
        float v = x[i];
        __half hv = __float2half_rn(v);
        xh[i] = hv;
        xl[i] = __float2half_rn(v - __half2float(hv));
        return;
    }
    const float* s;
    __half* d;
    int n;
    if (which == 1)      { s = Wq; d = q16; n = DMODEL * QK_COLS; }
    else if (which == 2) { s = Wk; d = k16; n = DMODEL * QK_COLS; }
    else if (which == 3) { s = Wv; d = v16; n = DMODEL * THD; }
    else                 { s = Wo; d = o16; n = THD * DMODEL; }
    if (i < n) d[i] = __float2half_rn(s[i]);
}

__global__ void rope_tables_kernel(float* __restrict__ cosT, float* __restrict__ sinT) {
    int i = blockIdx.x * blockDim.x + threadIdx.x;
    if (i >= SEQ * 32) return;
    int t = i >> 5, j = i & 31;
    double invf = pow(10000.0, -(double)(2 * j) / 64.0);
    float f = (float)t * (float)invf;
    cosT[i] = (float)cos((double)f);
    sinT[i] = (float)sin((double)f);
}

// ---------------- GEMM tile geometry (BK=64, 2-stage) ----------------
#define GA_ST 72
#define GB_ST 136
#define O_AH 0
#define O_AL (128 * GA_ST)
#define O_B  (2 * 128 * GA_ST)
#define STG_EL (O_B + 64 * GB_ST)
#define GEMM_SMEM (2 * STG_EL * 2)

// ---------------- merged QKV projection GEMM (flattened grid.x: 16Q+16K+8V) ----------------
__global__ __launch_bounds__(256) void gemm_qkv_kernel(
    const __half* __restrict__ Ah, const __half* __restrict__ Al,
    const __half* __restrict__ Wq, const __half* __restrict__ Wk, const __half* __restrict__ Wv,
    __half* __restrict__ Qo, __half* __restrict__ Ko, __half* __restrict__ Vo,
    const float* __restrict__ cosT, const float* __restrict__ sinT)
{
    int bx = blockIdx.x;
    int z, bxl;
    if (bx < 16)      { z = 0; bxl = bx; }
    else if (bx < 32) { z = 1; bxl = bx - 16; }
    else              { z = 2; bxl = bx - 32; }
    const int N = (z == 2) ? THD : QK_COLS;
    const int K = DMODEL;
    const __half* B = (z == 0) ? Wq : (z == 1) ? Wk : Wv;
    __half* C = (z == 0) ? Qo : (z == 1) ? Ko : Vo;
    const float oscale = (z == 0) ? QSCALE_F : 1.0f;

    extern __shared__ __half smb[];
    const unsigned smB = (unsigned)__cvta_generic_to_shared(smb);
    const int tid = threadIdx.x, wid = tid >> 5, lane = tid & 31;
    const int wm = wid & 3, wn = wid >> 2;
    const int g = lane >> 2, t = lane & 3;
    const int bm0 = blockIdx.y * 128, bn0 = bxl * 128;

    float acc[2][8][4];
#pragma unroll
    for (int i = 0; i < 2; i++)
#pragma unroll
        for (int j = 0; j < 8; j++)
#pragma unroll
            for (int c = 0; c < 4; c++) acc[i][j][c] = 0.f;

    auto load_stage = [&](int kt, int stg) {
        const int k0 = kt * 64;
        const unsigned sb = smB + stg * (STG_EL * 2);
#pragma unroll
        for (int q = 0; q < 8; q++) {
            int fi = tid + q * 256;
            int u = fi >> 10, idx = fi & 1023;
            int r = idx >> 3, c = (idx & 7) * 8;
            cp16(sb + ((u ? O_AL : O_AH) + r * GA_ST + c) * 2,
                 (u ? Al : Ah) + (size_t)(bm0 + r) * K + k0 + c);
        }
#pragma unroll
        for (int q = 0; q < 4; q++) {
            int fi = tid + q * 256;
            int r = fi >> 4, c = (fi & 15) * 8;
            cp16(sb + (O_B + r * GB_ST + c) * 2,
                 B + (size_t)(k0 + r) * N + bn0 + c);
        }
        cpcommit();
    };
    const int NT = K >> 6;
    load_stage(0, 0);

    const unsigned aoff = ((lane & 15) * GA_ST + (lane >> 4) * 8) * 2;
    const unsigned boff = (((((lane >> 3) & 1) * 8) + (lane & 7)) * GB_ST + (lane >> 4) * 8) * 2;

    for (int kt = 0; kt < NT; kt++) {
        asm volatile("cp.async.wait_group 0;");
        __syncthreads();
        if (kt + 1 < NT) load_stage(kt + 1, (kt + 1) & 1);

        const unsigned sb = smB + (kt & 1) * (STG_EL * 2);
#pragma unroll
        for (int ks = 0; ks < 4; ks++) {
            unsigned AH[2][4], AL[2][4];
#pragma unroll
            for (int mf = 0; mf < 2; mf++) {
                unsigned a = sb + (wm * 32 + mf * 16) * GA_ST * 2 + aoff + ks * 32;
                ldsm4(AH[mf][0], AH[mf][1], AH[mf][2], AH[mf][3], a + O_AH * 2);
                ldsm4(AL[mf][0], AL[mf][1], AL[mf][2], AL[mf][3], a + O_AL * 2);
            }
#pragma unroll
            for (int np = 0; np < 4; np++) {
                unsigned bofs = sb + boff + ks * 16 * GB_ST * 2 + O_B * 2 + (wn * 64 + np * 16) * 2;
                unsigned TB[4];
                ldsmT4(TB[0], TB[1], TB[2], TB[3], bofs);
#pragma unroll
                for (int hh = 0; hh < 2; hh++) {
                    int nf = np * 2 + hh;
#pragma unroll
                    for (int mf = 0; mf < 2; mf++) {
                        mma16h(acc[mf][nf], AH[mf], TB[2 * hh], TB[2 * hh + 1]);
                        mma16h(acc[mf][nf], AL[mf], TB[2 * hh], TB[2 * hh + 1]);
                    }
                }
            }
        }
    }

#pragma unroll
    for (int mf = 0; mf < 2; mf++) {
#pragma unroll
        for (int half = 0; half < 2; half++) {
            size_t row = (size_t)(bm0 + wm * 32 + mf * 16 + g + 8 * half);
            if (z < 2) {
                int s = (int)(row & (SEQ - 1));
#pragma unroll
                for (int nf = 0; nf < 4; nf++) {
                    int d = nf * 8 + 2 * t;
                    float2 cc = *(const float2*)&cosT[s * 32 + d];
                    float2 ss = *(const float2*)&sinT[s * 32 + d];
                    float lo0 = acc[mf][nf][2 * half], lo1 = acc[mf][nf][2 * half + 1];
                    float hi0 = acc[mf][nf + 4][2 * half], hi1 = acc[mf][nf + 4][2 * half + 1];
                    int c0 = bn0 + wn * 64 + d;
                    *(__half2*)&C[row * N + c0] = __floats2half2_rn(
                        (lo0 * cc.x - hi0 * ss.x) * oscale, (lo1 * cc.y - hi1 * ss.y) * oscale);
                    *(__half2*)&C[row * N + c0 + 32] = __floats2half2_rn(
                        (hi0 * cc.x + lo0 * ss.x) * oscale, (hi1 * cc.y + lo1 * ss.y) * oscale);
                }
            } else {
#pragma unroll
                for (int nf = 0; nf < 8; nf++) {
                    int c = bn0 + wn * 64 + nf * 8 + 2 * t;
                    *(__half2*)&C[row * N + c] =
                        __floats2half2_rn(acc[mf][nf][2 * half], acc[mf][nf][2 * half + 1]);
                }
            }
        }
    }
}

// ---------------- Wo GEMM (f32 out) ----------------
__global__ __launch_bounds__(256) void gemm_o_kernel(
    const __half* __restrict__ Ah, const __half* __restrict__ Al,
    const __half* __restrict__ B, float* __restrict__ C, int M, int N, int K)
{
    extern __shared__ __half smb[];
    const unsigned smB = (unsigned)__cvta_generic_to_shared(smb);
    const int tid = threadIdx.x, wid = tid >> 5, lane = tid & 31;
    const int wm = wid & 3, wn = wid >> 2;
    const int g = lane >> 2, t = lane & 3;
    const int bm0 = blockIdx.y * 128, bn0 = blockIdx.x * 128;

    float acc[2][8][4];
#pragma unroll
    for (int i = 0; i < 2; i++)
#pragma unroll
        for (int j = 0; j < 8; j++)
#pragma unroll
            for (int c = 0; c < 4; c++) acc[i][j][c] = 0.f;

    auto load_stage = [&](int kt, int stg) {
        const int k0 = kt * 64;
        const unsigned sb = smB + stg * (STG_EL * 2);
#pragma unroll
        for (int q = 0; q < 8; q++) {
            int fi = tid + q * 256;
            int u = fi >> 10, idx = fi & 1023;
            int r = idx >> 3, c = (idx & 7) * 8;
            cp16(sb + ((u ? O_AL : O_AH) + r * GA_ST + c) * 2,
                 (u ? Al : Ah) + (size_t)(bm0 + r) * K + k0 + c);
        }
#pragma unroll
        for (int q = 0; q < 4; q++) {
            int fi = tid + q * 256;
            int r = fi >> 4, c = (fi & 15) * 8;
            cp16(sb + (O_B + r * GB_ST + c) * 2,
                 B + (size_t)(k0 + r) * N + bn0 + c);
        }
        cpcommit();
    };
    const int NT = K >> 6;
    load_stage(0, 0);

    const unsigned aoff = ((lane & 15) * GA_ST + (lane >> 4) * 8) * 2;
    const unsigned boff = (((((lane >> 3) & 1) * 8) + (lane & 7)) * GB_ST + (lane >> 4) * 8) * 2;

    for (int kt = 0; kt < NT; kt++) {
        asm volatile("cp.async.wait_group 0;");
        __syncthreads();
        if (kt + 1 < NT) load_stage(kt + 1, (kt + 1) & 1);

        const unsigned sb = smB + (kt & 1) * (STG_EL * 2);
#pragma unroll
        for (int ks = 0; ks < 4; ks++) {
            unsigned AH[2][4], AL[2][4];
#pragma unroll
            for (int mf = 0; mf < 2; mf++) {
                unsigned a = sb + (wm * 32 + mf * 16) * GA_ST * 2 + aoff + ks * 32;
                ldsm4(AH[mf][0], AH[mf][1], AH[mf][2], AH[mf][3], a + O_AH * 2);
                ldsm4(AL[mf][0], AL[mf][1], AL[mf][2], AL[mf][3], a + O_AL * 2);
            }
#pragma unroll
            for (int np = 0; np < 4; np++) {
                unsigned bofs = sb + boff + ks * 16 * GB_ST * 2 + O_B * 2 + (wn * 64 + np * 16) * 2;
                unsigned TB[4];
                ldsmT4(TB[0], TB[1], TB[2], TB[3], bofs);
#pragma unroll
                for (int hh = 0; hh < 2; hh++) {
                    int nf = np * 2 + hh;
#pragma unroll
                    for (int mf = 0; mf < 2; mf++) {
                        mma16h(acc[mf][nf], AH[mf], TB[2 * hh], TB[2 * hh + 1]);
                        mma16h(acc[mf][nf], AL[mf], TB[2 * hh], TB[2 * hh + 1]);
                    }
                }
            }
        }
    }

#pragma unroll
    for (int mf = 0; mf < 2; mf++) {
        size_t r0 = (size_t)(bm0 + wm * 32 + mf * 16 + g);
#pragma unroll
        for (int nf = 0; nf < 8; nf++) {
            int c = bn0 + wn * 64 + nf * 8 + 2 * t;
            *(float2*)&C[r0 * N + c]       = make_float2(acc[mf][nf][0], acc[mf][nf][1]);
            *(float2*)&C[(r0 + 8) * N + c] = make_float2(acc[mf][nf][2], acc[mf][nf][3]);
        }
    }
}

// ---------------- fp16 differential flash attention v9 ----------------
// 64-row q tile, 16 rows/warp (one m-fragment) -> ~110 regs, 2 CTAs/SM.
#define HROW 144
#define QTILE 9216                      // 64 rows x 144 B
#define ST_STRIDE 27648                 // K1,K2,V tiles
#define ATT_SMEM (2 * QTILE + 2 * ST_STRIDE)   // 73728 B
#define NKT (SEQ / 64)

__global__ __launch_bounds__(256, 2) void attn_v9_kernel(
    const __half* __restrict__ Q, const __half* __restrict__ K, const __half* __restrict__ V,
    const float* __restrict__ lq1, const float* __restrict__ lk1,
    const float* __restrict__ lq2, const float* __restrict__ lk2,
    const float* __restrict__ lam_init_p,
    const float* __restrict__ gnw, const float* __restrict__ gnb,
    __half* __restrict__ OutH, __half* __restrict__ OutL)
{
    extern __shared__ char smv[];
    const unsigned smBase = (unsigned)__cvta_generic_to_shared(smv);
    const int tid = threadIdx.x, wid = tid >> 5, lane = tid & 31;
    const int br = wid >> 2, mblk = wid & 3;
    const int g = lane >> 2, t = lane & 3;
    const int bh = blockIdx.y, b = bh >> 4, h = bh & 15;
    const int q0 = blockIdx.x * 64;
    const int rowg0 = b * SEQ;
    const int c1base = h * HDIM;

    // prologue: Q1 (64x64 halves) at 0, Q2 at QTILE
#pragma unroll
    for (int q = 0; q < 2; q++) {
        int fi = tid + q * 256;                 // 0..511
        int r = fi >> 3, c = fi & 7;
        const __half* gq = &Q[(size_t)(rowg0 + q0 + r) * QK_COLS + c1base + c * 8];
        cp16(smBase + r * HROW + c * 16, gq);
        cp16(smBase + QTILE + r * HROW + c * 16, gq + THD);
    }
    auto load_stage = [&](int kt, int stg) {
        const int k0 = kt * 64;
        const unsigned base = smBase + 2 * QTILE + stg * ST_STRIDE;
#pragma unroll
        for (int q = 0; q < 2; q++) {
            int fi = tid + q * 256;
            int r = fi >> 3, c = fi & 7;
            const __half* gk = &K[(size_t)(rowg0 + k0 + r) * QK_COLS + c1base + c * 8];
            cp16(base + r * HROW + c * 16, gk);
            cp16(base + QTILE + r * HROW + c * 16, gk + THD);
            cp16(base + 2 * QTILE + r * HROW + c * 16,
                 &V[(size_t)(rowg0 + k0 + r) * THD + c1base + c * 8]);
        }
        cpcommit();
    };
    load_stage(0, 0);

    const unsigned aoff = (lane & 15) * HROW + (lane >> 4) * 16;
    const unsigned boff = ((lane & 7) + ((lane >> 4) << 3)) * HROW + ((lane >> 3) & 1) * 16;
    const unsigned boffT = (((lane & 7) + (((lane >> 3) & 1) << 3)) * HROW) + (lane >> 4) * 16;
    const unsigned aQw = smBase + br * QTILE + mblk * 16 * HROW + aoff;

    float O[8][4];
#pragma unroll
    for (int df = 0; df < 8; df++)
#pragma unroll
        for (int c = 0; c < 4; c++) O[df][c] = 0.f;
    float mmx0 = -1e30f, mmx1 = -1e30f;
    float lsA[4] = {0.f, 0.f, 0.f, 0.f};

    for (int kt = 0; kt < NKT; kt++) {
        asm volatile("cp.async.wait_group 0;");
        __syncthreads();
        if (kt + 1 < NKT) load_stage(kt + 1, (kt + 1) & 1);

        const unsigned stb = smBase + 2 * QTILE + (kt & 1) * ST_STRIDE;
        const unsigned kB = stb + br * QTILE + boff;
        const unsigned vB = stb + 2 * QTILE + boffT;

        float S[8][4];
#pragma unroll
        for (int nf = 0; nf < 8; nf++)
#pragma unroll
            for (int c = 0; c < 4; c++) S[nf][c] = 0.f;

#pragma unroll
        for (int p = 0; p < 4; p++) {
            unsigned A[4];
            ldsm4(A[0], A[1], A[2], A[3], aQw + p * 32);
#pragma unroll
            for (int nb = 0; nb < 4; nb++) {
                unsigned Bf[4];
                ldsm4(Bf[0], Bf[1], Bf[2], Bf[3], kB + nb * 16 * HROW + p * 32);
                mma16h(S[2 * nb],     A, Bf[0], Bf[1]);
                mma16h(S[2 * nb + 1], A, Bf[2], Bf[3]);
            }
        }

        // exp2-domain softmax
        unsigned P2[8][2];
        {
            float mx0 = -1e30f, mx1 = -1e30f;
#pragma unroll
            for (int nf = 0; nf < 8; nf++) {
                mx0 = fmaxf(mx0, fmaxf(S[nf][0], S[nf][1]));
                mx1 = fmaxf(mx1, fmaxf(S[nf][2], S[nf][3]));
            }
            __half2 mp = __floats2half2_rn(mx0, mx1);
            unsigned mu = *(unsigned*)&mp;
            unsigned o1 = __shfl_xor_sync(0xffffffffu, mu, 1);
            mp = __hmax2(mp, *(__half2*)&o1);
            mu = *(unsigned*)&mp;
            o1 = __shfl_xor_sync(0xffffffffu, mu, 2);
            mp = __hmax2(mp, *(__half2*)&o1);
            mx0 = __low2float(mp);
            mx1 = __high2float(mp);
            float mn0 = fmaxf(mmx0, mx0);
            float mn1 = fmaxf(mmx1, mx1);
            float c0 = exp2f(mmx0 - mn0);
            float c1 = exp2f(mmx1 - mn1);
            mmx0 = mn0; mmx1 = mn1;
            lsA[0] *= c0; lsA[1] *= c0;
            lsA[2] *= c1; lsA[3] *= c1;
#pragma unroll
            for (int nf = 0; nf < 8; nf++) {
                P2[nf][0] = h2exp2(packsub(S[nf][0], S[nf][1], mn0));
                P2[nf][1] = h2exp2(packsub(S[nf][2], S[nf][3], mn1));
            }
#pragma unroll
            for (int df = 0; df < 8; df++) {
                O[df][0] *= c0; O[df][1] *= c0;
                O[df][2] *= c1; O[df][3] *= c1;
            }
        }

#pragma unroll
        for (int p = 0; p < 4; p++) {
            unsigned PA[4];
            PA[0] = P2[2 * p][0];
            PA[1] = P2[2 * p][1];
            PA[2] = P2[2 * p + 1][0];
            PA[3] = P2[2 * p + 1][1];
            mma16h(lsA, PA, ONES16, ONES16);
#pragma unroll
            for (int nb = 0; nb < 4; nb++) {
                unsigned Bf[4];
                ldsmT4(Bf[0], Bf[1], Bf[2], Bf[3], vB + p * 16 * HROW + nb * 32);
                mma16h(O[2 * nb],     PA, Bf[0], Bf[1]);
                mma16h(O[2 * nb + 1], PA, Bf[2], Bf[3]);
            }
        }
    }

    const float lam_init = lam_init_p[0];
    const float lam = __expf(lq1[h] * lk1[h]) - __expf(lq2[h] * lk2[h]) + lam_init;
    const float osc = 1.0f - lam_init;
    float* Ex = (float*)(smv + 2 * QTILE);   // 64 x 68 f32 = 17408 B, fits stage area

    __syncthreads();   // all warps out of mainloop before Ex reuses stage smem
    if (br == 1) {
        float inv0 = lam / lsA[0];
        float inv1 = lam / lsA[2];
        int row0 = mblk * 16 + g;
#pragma unroll
        for (int df = 0; df < 8; df++) {
            int col = df * 8 + 2 * t;
            *(float2*)&Ex[row0 * 68 + col] = make_float2(O[df][0] * inv0, O[df][1] * inv0);
            *(float2*)&Ex[(row0 + 8) * 68 + col] = make_float2(O[df][2] * inv1, O[df][3] * inv1);
        }
    }
    __syncthreads();
    if (br == 0) {
#pragma unroll
        for (int half = 0; half < 2; half++) {
            float inv1 = 1.0f / lsA[2 * half];
            int lrow = mblk * 16 + g + 8 * half;
            float v[16];
            float s = 0.f, sq = 0.f;
#pragma unroll
            for (int df = 0; df < 8; df++) {
                float2 e = *(float2*)&Ex[lrow * 68 + df * 8 + 2 * t];
                float a0 = O[df][half * 2 + 0] * inv1 - e.x;
                float a1 = O[df][half * 2 + 1] * inv1 - e.y;
                v[2 * df] = a0; v[2 * df + 1] = a1;
                s += a0 + a1; sq += a0 * a0 + a1 * a1;
            }
            s  += __shfl_xor_sync(0xffffffffu, s, 1);
            s  += __shfl_xor_sync(0xffffffffu, s, 2);
            sq += __shfl_xor_sync(0xffffffffu, sq, 1);
            sq += __shfl_xor_sync(0xffffffffu, sq, 2);
            float mean = s * (1.0f / 64.0f);
            float var = sq * (1.0f / 64.0f) - mean * mean;
            float istd = rsqrtf(var + GN_EPS);
            size_t grow = (size_t)(rowg0 + q0 + lrow);
#pragma unroll
            for (int df = 0; df < 8; df++) {
                int col = h * HDIM + df * 8 + 2 * t;
                float2 gw = *(const float2*)&gnw[col];
                float2 gb = *(const float2*)&gnb[col];
                float o0 = ((v[2 * df]     - mean) * istd * gw.x + gb.x) * osc;
                float o1 = ((v[2 * df + 1] - mean) * istd * gw.y + gb.y) * osc;
                __half h0 = __float2half_rn(o0);
                __half h1 = __float2half_rn(o1);
                __half2 ph; ph.x = h0; ph.y = h1;
                __half2 pl;
                pl.x = __float2half_rn(o0 - __half2float(h0));
                pl.y = __float2half_rn(o1 - __half2float(h1));
                *(__half2*)&OutH[grow * THD + col] = ph;
                *(__half2*)&OutL[grow * THD + col] = pl;
            }
        }
    }
}

// ---------------- kernel_launch ----------------
extern "C" void kernel_launch(void* const* d_in, const int* in_sizes, int n_in,
                              void* d_out, int out_size)
{
    const float* x   = (const float*)d_in[0];
    const float* Wq  = (const float*)d_in[1];
    const float* Wk  = (const float*)d_in[2];
    const float* Wv  = (const float*)d_in[3];
    const float* Wo  = (const float*)d_in[4];
    const float* lq1 = (const float*)d_in[5];
    const float* lk1 = (const float*)d_in[6];
    const float* lq2 = (const float*)d_in[7];
    const float* lk2 = (const float*)d_in[8];
    const float* lam = (const float*)d_in[9];
    const float* gnw = (const float*)d_in[10];
    const float* gnb = (const float*)d_in[11];
    float* out = (float*)d_out;

    float *cosT, *sinT;
    __half *Qh, *Kh, *V16, *xh, *xl, *Wq16, *Wk16, *Wv16, *Wo16, *Ah, *Al;
    cudaGetSymbolAddress((void**)&Qh, g_Qh);
    cudaGetSymbolAddress((void**)&Kh, g_Kh);
    cudaGetSymbolAddress((void**)&V16, g_V16);
    cudaGetSymbolAddress((void**)&cosT, g_cosT);
    cudaGetSymbolAddress((void**)&sinT, g_sinT);
    cudaGetSymbolAddress((void**)&xh, g_xh);
    cudaGetSymbolAddress((void**)&xl, g_xl);
    cudaGetSymbolAddress((void**)&Wq16, g_Wq16);
    cudaGetSymbolAddress((void**)&Wk16, g_Wk16);
    cudaGetSymbolAddress((void**)&Wv16, g_Wv16);
    cudaGetSymbolAddress((void**)&Wo16, g_Wo16);
    cudaGetSymbolAddress((void**)&Ah, g_Ah);
    cudaGetSymbolAddress((void**)&Al, g_Al);

    cudaFuncSetAttribute(attn_v9_kernel, cudaFuncAttributeMaxDynamicSharedMemorySize, ATT_SMEM);
    cudaFuncSetAttribute(gemm_qkv_kernel, cudaFuncAttributeMaxDynamicSharedMemorySize, GEMM_SMEM);
    cudaFuncSetAttribute(gemm_o_kernel, cudaFuncAttributeMaxDynamicSharedMemorySize, GEMM_SMEM);

    rope_tables_kernel<<<(SEQ * 32 + 255) / 256, 256>>>(cosT, sinT);
    prep_kernel<<<dim3((MROWS * DMODEL + 255) / 256, 5), 256>>>(
        x, Wq, Wk, Wv, Wo, xh, xl, Wq16, Wk16, Wv16, Wo16);

    gemm_qkv_kernel<<<dim3(40, MROWS / 128), 256, GEMM_SMEM>>>(
        xh, xl, Wq16, Wk16, Wv16, Qh, Kh, V16, cosT, sinT);

    attn_v9_kernel<<<dim3(SEQ / 64, BATCH * NHEAD), 256, ATT_SMEM>>>(
        Qh, Kh, V16, lq1, lk1, lq2, lk2, lam, gnw, gnb, Ah, Al);

    gemm_o_kernel<<<dim3(DMODEL / 128, MROWS / 128), 256, GEMM_SMEM>>>(
        Ah, Al, Wo16, out, MROWS, DMODEL, THD);
}

// round 17
// speedup vs baseline: 1.0371x; 1.0189x over previous
#include <cuda_runtime.h>
#include <cuda_fp16.h>
#include <cstdint>
#include <math.h>

#define BATCH 2
#define SEQ   2048
#define DMODEL 1024
#define NHEAD 16
#define HDIM  64
#define THD   (NHEAD * HDIM)
#define MROWS (BATCH * SEQ)
#define QK_COLS (2 * THD)
#define GN_EPS 1e-5f
#define QSCALE_F 0.18033688f   // 0.125 * log2(e)
#define ONES16 0x3C003C00u     // half2(1.0, 1.0)

// ---------------- scratch ----------------
__device__ __half g_Qh[MROWS * QK_COLS];
__device__ __half g_Kh[MROWS * QK_COLS];
__device__ __half g_V16[MROWS * THD];
__device__ float g_cosT[SEQ * 32];
__device__ float g_sinT[SEQ * 32];
__device__ __half g_xh[MROWS * DMODEL],  g_xl[MROWS * DMODEL];
__device__ __half g_Wq16[DMODEL * QK_COLS];
__device__ __half g_Wk16[DMODEL * QK_COLS];
__device__ __half g_Wv16[DMODEL * THD];
__device__ __half g_Wo16[THD * DMODEL];
__device__ __half g_Ah[MROWS * THD], g_Al[MROWS * THD];

// ---------------- helpers ----------------
__device__ __forceinline__ void ldsm4(unsigned &r0, unsigned &r1, unsigned &r2, unsigned &r3, unsigned a) {
    asm volatile("ldmatrix.sync.aligned.m8n8.x4.shared.b16 {%0,%1,%2,%3}, [%4];"
        : "=r"(r0), "=r"(r1), "=r"(r2), "=r"(r3) : "r"(a));
}
__device__ __forceinline__ void ldsmT4(unsigned &r0, unsigned &r1, unsigned &r2, unsigned &r3, unsigned a) {
    asm volatile("ldmatrix.sync.aligned.m8n8.x4.trans.shared.b16 {%0,%1,%2,%3}, [%4];"
        : "=r"(r0), "=r"(r1), "=r"(r2), "=r"(r3) : "r"(a));
}
__device__ __forceinline__ void mma16h(float* c, const unsigned* a, unsigned b0, unsigned b1) {
    asm volatile("mma.sync.aligned.m16n8k16.row.col.f32.f16.f16.f32 "
        "{%0,%1,%2,%3},{%4,%5,%6,%7},{%8,%9},{%0,%1,%2,%3};"
        : "+f"(c[0]), "+f"(c[1]), "+f"(c[2]), "+f"(c[3])
        : "r"(a[0]), "r"(a[1]), "r"(a[2]), "r"(a[3]), "r"(b0), "r"(b1));
}
__device__ __forceinline__ void cp16(unsigned s, const void* g) {
    asm volatile("cp.async.cg.shared.global [%0], [%1], 16;" :: "r"(s), "l"(g));
}
__device__ __forceinline__ void cpcommit() { asm volatile("cp.async.commit_group;"); }
__device__ __forceinline__ unsigned h2exp2(unsigned x) {
    unsigned r;
    asm("ex2.approx.f16x2 %0, %1;" : "=r"(r) : "r"(x));
    return r;
}
__device__ __forceinline__ unsigned packsub(float a, float b, float m) {
    __half2 h = __floats2half2_rn(a - m, b - m);
    return *(unsigned*)&h;
}

// ---------------- fused input-split + weight-convert ----------------
__global__ void prep_kernel(const float* __restrict__ x,
                            const float* __restrict__ Wq, const float* __restrict__ Wk,
                            const float* __restrict__ Wv, const float* __restrict__ Wo,
                            __half* __restrict__ xh, __half* __restrict__ xl,
                            __half* __restrict__ q16, __half* __restrict__ k16,
                            __half* __restrict__ v16, __half* __restrict__ o16) {
    int which = blockIdx.y;
    int i = blockIdx.x * blockDim.x + threadIdx.x;
    if (which == 0) {
        if (i >= MROWS * DMODEL) return;
        float v = x[i];
        __half hv = __float2half_rn(v);
        xh[i] = hv;
        xl[i] = __float2half_rn(v - __half2float(hv));
        return;
    }
    const float* s;
    __half* d;
    int n;
    if (which == 1)      { s = Wq; d = q16; n = DMODEL * QK_COLS; }
    else if (which == 2) { s = Wk; d = k16; n = DMODEL * QK_COLS; }
    else if (which == 3) { s = Wv; d = v16; n = DMODEL * THD; }
    else                 { s = Wo; d = o16; n = THD * DMODEL; }
    if (i < n) d[i] = __float2half_rn(s[i]);
}

__global__ void rope_tables_kernel(float* __restrict__ cosT, float* __restrict__ sinT) {
    int i = blockIdx.x * blockDim.x + threadIdx.x;
    if (i >= SEQ * 32) return;
    int t = i >> 5, j = i & 31;
    double invf = pow(10000.0, -(double)(2 * j) / 64.0);
    float f = (float)t * (float)invf;
    cosT[i] = (float)cos((double)f);
    sinT[i] = (float)sin((double)f);
}

// ---------------- GEMM tile geometry (BK=64, 2-stage) ----------------
#define GA_ST 72
#define GB_ST 136
#define O_AH 0
#define O_AL (128 * GA_ST)
#define O_B  (2 * 128 * GA_ST)
#define STG_EL (O_B + 64 * GB_ST)
#define GEMM_SMEM (2 * STG_EL * 2)

// ---------------- merged QKV projection GEMM (flattened grid.x: 16Q+16K+8V) ----------------
__global__ __launch_bounds__(256) void gemm_qkv_kernel(
    const __half* __restrict__ Ah, const __half* __restrict__ Al,
    const __half* __restrict__ Wq, const __half* __restrict__ Wk, const __half* __restrict__ Wv,
    __half* __restrict__ Qo, __half* __restrict__ Ko, __half* __restrict__ Vo,
    const float* __restrict__ cosT, const float* __restrict__ sinT)
{
    int bx = blockIdx.x;
    int z, bxl;
    if (bx < 16)      { z = 0; bxl = bx; }
    else if (bx < 32) { z = 1; bxl = bx - 16; }
    else              { z = 2; bxl = bx - 32; }
    const int N = (z == 2) ? THD : QK_COLS;
    const int K = DMODEL;
    const __half* B = (z == 0) ? Wq : (z == 1) ? Wk : Wv;
    __half* C = (z == 0) ? Qo : (z == 1) ? Ko : Vo;
    const float oscale = (z == 0) ? QSCALE_F : 1.0f;

    extern __shared__ __half smb[];
    const unsigned smB = (unsigned)__cvta_generic_to_shared(smb);
    const int tid = threadIdx.x, wid = tid >> 5, lane = tid & 31;
    const int wm = wid & 3, wn = wid >> 2;
    const int g = lane >> 2, t = lane & 3;
    const int bm0 = blockIdx.y * 128, bn0 = bxl * 128;

    float acc[2][8][4];
#pragma unroll
    for (int i = 0; i < 2; i++)
#pragma unroll
        for (int j = 0; j < 8; j++)
#pragma unroll
            for (int c = 0; c < 4; c++) acc[i][j][c] = 0.f;

    auto load_stage = [&](int kt, int stg) {
        const int k0 = kt * 64;
        const unsigned sb = smB + stg * (STG_EL * 2);
#pragma unroll
        for (int q = 0; q < 8; q++) {
            int fi = tid + q * 256;
            int u = fi >> 10, idx = fi & 1023;
            int r = idx >> 3, c = (idx & 7) * 8;
            cp16(sb + ((u ? O_AL : O_AH) + r * GA_ST + c) * 2,
                 (u ? Al : Ah) + (size_t)(bm0 + r) * K + k0 + c);
        }
#pragma unroll
        for (int q = 0; q < 4; q++) {
            int fi = tid + q * 256;
            int r = fi >> 4, c = (fi & 15) * 8;
            cp16(sb + (O_B + r * GB_ST + c) * 2,
                 B + (size_t)(k0 + r) * N + bn0 + c);
        }
        cpcommit();
    };
    const int NT = K >> 6;
    load_stage(0, 0);

    const unsigned aoff = ((lane & 15) * GA_ST + (lane >> 4) * 8) * 2;
    const unsigned boff = (((((lane >> 3) & 1) * 8) + (lane & 7)) * GB_ST + (lane >> 4) * 8) * 2;

    for (int kt = 0; kt < NT; kt++) {
        asm volatile("cp.async.wait_group 0;");
        __syncthreads();
        if (kt + 1 < NT) load_stage(kt + 1, (kt + 1) & 1);

        const unsigned sb = smB + (kt & 1) * (STG_EL * 2);
#pragma unroll
        for (int ks = 0; ks < 4; ks++) {
            unsigned AH[2][4], AL[2][4];
#pragma unroll
            for (int mf = 0; mf < 2; mf++) {
                unsigned a = sb + (wm * 32 + mf * 16) * GA_ST * 2 + aoff + ks * 32;
                ldsm4(AH[mf][0], AH[mf][1], AH[mf][2], AH[mf][3], a + O_AH * 2);
                ldsm4(AL[mf][0], AL[mf][1], AL[mf][2], AL[mf][3], a + O_AL * 2);
            }
#pragma unroll
            for (int np = 0; np < 4; np++) {
                unsigned bofs = sb + boff + ks * 16 * GB_ST * 2 + O_B * 2 + (wn * 64 + np * 16) * 2;
                unsigned TB[4];
                ldsmT4(TB[0], TB[1], TB[2], TB[3], bofs);
#pragma unroll
                for (int hh = 0; hh < 2; hh++) {
                    int nf = np * 2 + hh;
#pragma unroll
                    for (int mf = 0; mf < 2; mf++) {
                        mma16h(acc[mf][nf], AH[mf], TB[2 * hh], TB[2 * hh + 1]);
                        mma16h(acc[mf][nf], AL[mf], TB[2 * hh], TB[2 * hh + 1]);
                    }
                }
            }
        }
    }

#pragma unroll
    for (int mf = 0; mf < 2; mf++) {
#pragma unroll
        for (int half = 0; half < 2; half++) {
            size_t row = (size_t)(bm0 + wm * 32 + mf * 16 + g + 8 * half);
            if (z < 2) {
                int s = (int)(row & (SEQ - 1));
#pragma unroll
                for (int nf = 0; nf < 4; nf++) {
                    int d = nf * 8 + 2 * t;
                    float2 cc = *(const float2*)&cosT[s * 32 + d];
                    float2 ss = *(const float2*)&sinT[s * 32 + d];
                    float lo0 = acc[mf][nf][2 * half], lo1 = acc[mf][nf][2 * half + 1];
                    float hi0 = acc[mf][nf + 4][2 * half], hi1 = acc[mf][nf + 4][2 * half + 1];
                    int c0 = bn0 + wn * 64 + d;
                    *(__half2*)&C[row * N + c0] = __floats2half2_rn(
                        (lo0 * cc.x - hi0 * ss.x) * oscale, (lo1 * cc.y - hi1 * ss.y) * oscale);
                    *(__half2*)&C[row * N + c0 + 32] = __floats2half2_rn(
                        (hi0 * cc.x + lo0 * ss.x) * oscale, (hi1 * cc.y + lo1 * ss.y) * oscale);
                }
            } else {
#pragma unroll
                for (int nf = 0; nf < 8; nf++) {
                    int c = bn0 + wn * 64 + nf * 8 + 2 * t;
                    *(__half2*)&C[row * N + c] =
                        __floats2half2_rn(acc[mf][nf][2 * half], acc[mf][nf][2 * half + 1]);
                }
            }
        }
    }
}

// ---------------- Wo GEMM (f32 out) ----------------
__global__ __launch_bounds__(256) void gemm_o_kernel(
    const __half* __restrict__ Ah, const __half* __restrict__ Al,
    const __half* __restrict__ B, float* __restrict__ C, int M, int N, int K)
{
    extern __shared__ __half smb[];
    const unsigned smB = (unsigned)__cvta_generic_to_shared(smb);
    const int tid = threadIdx.x, wid = tid >> 5, lane = tid & 31;
    const int wm = wid & 3, wn = wid >> 2;
    const int g = lane >> 2, t = lane & 3;
    const int bm0 = blockIdx.y * 128, bn0 = blockIdx.x * 128;

    float acc[2][8][4];
#pragma unroll
    for (int i = 0; i < 2; i++)
#pragma unroll
        for (int j = 0; j < 8; j++)
#pragma unroll
            for (int c = 0; c < 4; c++) acc[i][j][c] = 0.f;

    auto load_stage = [&](int kt, int stg) {
        const int k0 = kt * 64;
        const unsigned sb = smB + stg * (STG_EL * 2);
#pragma unroll
        for (int q = 0; q < 8; q++) {
            int fi = tid + q * 256;
            int u = fi >> 10, idx = fi & 1023;
            int r = idx >> 3, c = (idx & 7) * 8;
            cp16(sb + ((u ? O_AL : O_AH) + r * GA_ST + c) * 2,
                 (u ? Al : Ah) + (size_t)(bm0 + r) * K + k0 + c);
        }
#pragma unroll
        for (int q = 0; q < 4; q++) {
            int fi = tid + q * 256;
            int r = fi >> 4, c = (fi & 15) * 8;
            cp16(sb + (O_B + r * GB_ST + c) * 2,
                 B + (size_t)(k0 + r) * N + bn0 + c);
        }
        cpcommit();
    };
    const int NT = K >> 6;
    load_stage(0, 0);

    const unsigned aoff = ((lane & 15) * GA_ST + (lane >> 4) * 8) * 2;
    const unsigned boff = (((((lane >> 3) & 1) * 8) + (lane & 7)) * GB_ST + (lane >> 4) * 8) * 2;

    for (int kt = 0; kt < NT; kt++) {
        asm volatile("cp.async.wait_group 0;");
        __syncthreads();
        if (kt + 1 < NT) load_stage(kt + 1, (kt + 1) & 1);

        const unsigned sb = smB + (kt & 1) * (STG_EL * 2);
#pragma unroll
        for (int ks = 0; ks < 4; ks++) {
            unsigned AH[2][4], AL[2][4];
#pragma unroll
            for (int mf = 0; mf < 2; mf++) {
                unsigned a = sb + (wm * 32 + mf * 16) * GA_ST * 2 + aoff + ks * 32;
                ldsm4(AH[mf][0], AH[mf][1], AH[mf][2], AH[mf][3], a + O_AH * 2);
                ldsm4(AL[mf][0], AL[mf][1], AL[mf][2], AL[mf][3], a + O_AL * 2);
            }
#pragma unroll
            for (int np = 0; np < 4; np++) {
                unsigned bofs = sb + boff + ks * 16 * GB_ST * 2 + O_B * 2 + (wn * 64 + np * 16) * 2;
                unsigned TB[4];
                ldsmT4(TB[0], TB[1], TB[2], TB[3], bofs);
#pragma unroll
                for (int hh = 0; hh < 2; hh++) {
                    int nf = np * 2 + hh;
#pragma unroll
                    for (int mf = 0; mf < 2; mf++) {
                        mma16h(acc[mf][nf], AH[mf], TB[2 * hh], TB[2 * hh + 1]);
                        mma16h(acc[mf][nf], AL[mf], TB[2 * hh], TB[2 * hh + 1]);
                    }
                }
            }
        }
    }

#pragma unroll
    for (int mf = 0; mf < 2; mf++) {
        size_t r0 = (size_t)(bm0 + wm * 32 + mf * 16 + g);
#pragma unroll
        for (int nf = 0; nf < 8; nf++) {
            int c = bn0 + wn * 64 + nf * 8 + 2 * t;
            *(float2*)&C[r0 * N + c]       = make_float2(acc[mf][nf][0], acc[mf][nf][1]);
            *(float2*)&C[(r0 + 8) * N + c] = make_float2(acc[mf][nf][2], acc[mf][nf][3]);
        }
    }
}

// ---------------- fp16 differential flash attention v10 ----------------
// 64-row q tile, 16 rows/warp; Q fragments hoisted (loaded once);
// P aliased into S registers; 2 CTAs/SM.
#define HROW 144
#define QTILE 9216
#define ST_STRIDE 27648
#define ATT_SMEM (2 * QTILE + 2 * ST_STRIDE)   // 73728 B
#define NKT (SEQ / 64)

__global__ __launch_bounds__(256, 2) void attn_v10_kernel(
    const __half* __restrict__ Q, const __half* __restrict__ K, const __half* __restrict__ V,
    const float* __restrict__ lq1, const float* __restrict__ lk1,
    const float* __restrict__ lq2, const float* __restrict__ lk2,
    const float* __restrict__ lam_init_p,
    const float* __restrict__ gnw, const float* __restrict__ gnb,
    __half* __restrict__ OutH, __half* __restrict__ OutL)
{
    extern __shared__ char smv[];
    const unsigned smBase = (unsigned)__cvta_generic_to_shared(smv);
    const int tid = threadIdx.x, wid = tid >> 5, lane = tid & 31;
    const int br = wid >> 2, mblk = wid & 3;
    const int g = lane >> 2, t = lane & 3;
    const int bh = blockIdx.y, b = bh >> 4, h = bh & 15;
    const int q0 = blockIdx.x * 64;
    const int rowg0 = b * SEQ;
    const int c1base = h * HDIM;

    // prologue: Q tiles (group 0), then stage 0 (group 1)
#pragma unroll
    for (int q = 0; q < 2; q++) {
        int fi = tid + q * 256;
        int r = fi >> 3, c = fi & 7;
        const __half* gq = &Q[(size_t)(rowg0 + q0 + r) * QK_COLS + c1base + c * 8];
        cp16(smBase + r * HROW + c * 16, gq);
        cp16(smBase + QTILE + r * HROW + c * 16, gq + THD);
    }
    cpcommit();
    auto load_stage = [&](int kt, int stg) {
        const int k0 = kt * 64;
        const unsigned base = smBase + 2 * QTILE + stg * ST_STRIDE;
#pragma unroll
        for (int q = 0; q < 2; q++) {
            int fi = tid + q * 256;
            int r = fi >> 3, c = fi & 7;
            const __half* gk = &K[(size_t)(rowg0 + k0 + r) * QK_COLS + c1base + c * 8];
            cp16(base + r * HROW + c * 16, gk);
            cp16(base + QTILE + r * HROW + c * 16, gk + THD);
            cp16(base + 2 * QTILE + r * HROW + c * 16,
                 &V[(size_t)(rowg0 + k0 + r) * THD + c1base + c * 8]);
        }
        cpcommit();
    };
    load_stage(0, 0);

    const unsigned aoff = (lane & 15) * HROW + (lane >> 4) * 16;
    const unsigned boff = ((lane & 7) + ((lane >> 4) << 3)) * HROW + ((lane >> 3) & 1) * 16;
    const unsigned boffT = (((lane & 7) + (((lane >> 3) & 1) << 3)) * HROW) + (lane >> 4) * 16;
    const unsigned aQw = smBase + br * QTILE + mblk * 16 * HROW + aoff;

    // hoist Q fragments (Q is invariant over k-tiles)
    asm volatile("cp.async.wait_group 1;");   // Q group done; stage 0 may still fly
    __syncthreads();
    unsigned QA[4][4];
#pragma unroll
    for (int p = 0; p < 4; p++)
        ldsm4(QA[p][0], QA[p][1], QA[p][2], QA[p][3], aQw + p * 32);

    float O[8][4];
#pragma unroll
    for (int df = 0; df < 8; df++)
#pragma unroll
        for (int c = 0; c < 4; c++) O[df][c] = 0.f;
    float mmx0 = -1e30f, mmx1 = -1e30f;
    float lsA[4] = {0.f, 0.f, 0.f, 0.f};

    for (int kt = 0; kt < NKT; kt++) {
        asm volatile("cp.async.wait_group 0;");
        __syncthreads();
        if (kt + 1 < NKT) load_stage(kt + 1, (kt + 1) & 1);

        const unsigned stb = smBase + 2 * QTILE + (kt & 1) * ST_STRIDE;
        const unsigned kB = stb + br * QTILE + boff;
        const unsigned vB = stb + 2 * QTILE + boffT;

        float S[8][4];
#pragma unroll
        for (int nf = 0; nf < 8; nf++)
#pragma unroll
            for (int c = 0; c < 4; c++) S[nf][c] = 0.f;

#pragma unroll
        for (int p = 0; p < 4; p++) {
#pragma unroll
            for (int nb = 0; nb < 4; nb++) {
                unsigned Bf[4];
                ldsm4(Bf[0], Bf[1], Bf[2], Bf[3], kB + nb * 16 * HROW + p * 32);
                mma16h(S[2 * nb],     QA[p], Bf[0], Bf[1]);
                mma16h(S[2 * nb + 1], QA[p], Bf[2], Bf[3]);
            }
        }

        // exp2-domain softmax; P written back into S (register alias)
        {
            float mx0 = -1e30f, mx1 = -1e30f;
#pragma unroll
            for (int nf = 0; nf < 8; nf++) {
                mx0 = fmaxf(mx0, fmaxf(S[nf][0], S[nf][1]));
                mx1 = fmaxf(mx1, fmaxf(S[nf][2], S[nf][3]));
            }
            __half2 mp = __floats2half2_rn(mx0, mx1);
            unsigned mu = *(unsigned*)&mp;
            unsigned o1 = __shfl_xor_sync(0xffffffffu, mu, 1);
            mp = __hmax2(mp, *(__half2*)&o1);
            mu = *(unsigned*)&mp;
            o1 = __shfl_xor_sync(0xffffffffu, mu, 2);
            mp = __hmax2(mp, *(__half2*)&o1);
            mx0 = __low2float(mp);
            mx1 = __high2float(mp);
            float mn0 = fmaxf(mmx0, mx0);
            float mn1 = fmaxf(mmx1, mx1);
            float c0 = exp2f(mmx0 - mn0);
            float c1 = exp2f(mmx1 - mn1);
            mmx0 = mn0; mmx1 = mn1;
            lsA[0] *= c0; lsA[1] *= c0;
            lsA[2] *= c1; lsA[3] *= c1;
#pragma unroll
            for (int nf = 0; nf < 8; nf++) {
                unsigned p0 = h2exp2(packsub(S[nf][0], S[nf][1], mn0));
                unsigned p1 = h2exp2(packsub(S[nf][2], S[nf][3], mn1));
                S[nf][0] = __uint_as_float(p0);
                S[nf][1] = __uint_as_float(p1);
            }
#pragma unroll
            for (int df = 0; df < 8; df++) {
                O[df][0] *= c0; O[df][1] *= c0;
                O[df][2] *= c1; O[df][3] *= c1;
            }
        }

#pragma unroll
        for (int p = 0; p < 4; p++) {
            unsigned PA[4];
            PA[0] = __float_as_uint(S[2 * p][0]);
            PA[1] = __float_as_uint(S[2 * p][1]);
            PA[2] = __float_as_uint(S[2 * p + 1][0]);
            PA[3] = __float_as_uint(S[2 * p + 1][1]);
            mma16h(lsA, PA, ONES16, ONES16);
#pragma unroll
            for (int nb = 0; nb < 4; nb++) {
                unsigned Bf[4];
                ldsmT4(Bf[0], Bf[1], Bf[2], Bf[3], vB + p * 16 * HROW + nb * 32);
                mma16h(O[2 * nb],     PA, Bf[0], Bf[1]);
                mma16h(O[2 * nb + 1], PA, Bf[2], Bf[3]);
            }
        }
    }

    const float lam_init = lam_init_p[0];
    const float lam = __expf(lq1[h] * lk1[h]) - __expf(lq2[h] * lk2[h]) + lam_init;
    const float osc = 1.0f - lam_init;
    float* Ex = (float*)(smv + 2 * QTILE);

    __syncthreads();
    if (br == 1) {
        float inv0 = lam / lsA[0];
        float inv1 = lam / lsA[2];
        int row0 = mblk * 16 + g;
#pragma unroll
        for (int df = 0; df < 8; df++) {
            int col = df * 8 + 2 * t;
            *(float2*)&Ex[row0 * 68 + col] = make_float2(O[df][0] * inv0, O[df][1] * inv0);
            *(float2*)&Ex[(row0 + 8) * 68 + col] = make_float2(O[df][2] * inv1, O[df][3] * inv1);
        }
    }
    __syncthreads();
    if (br == 0) {
#pragma unroll
        for (int half = 0; half < 2; half++) {
            float inv1 = 1.0f / lsA[2 * half];
            int lrow = mblk * 16 + g + 8 * half;
            float v[16];
            float s = 0.f, sq = 0.f;
#pragma unroll
            for (int df = 0; df < 8; df++) {
                float2 e = *(float2*)&Ex[lrow * 68 + df * 8 + 2 * t];
                float a0 = O[df][half * 2 + 0] * inv1 - e.x;
                float a1 = O[df][half * 2 + 1] * inv1 - e.y;
                v[2 * df] = a0; v[2 * df + 1] = a1;
                s += a0 + a1; sq += a0 * a0 + a1 * a1;
            }
            s  += __shfl_xor_sync(0xffffffffu, s, 1);
            s  += __shfl_xor_sync(0xffffffffu, s, 2);
            sq += __shfl_xor_sync(0xffffffffu, sq, 1);
            sq += __shfl_xor_sync(0xffffffffu, sq, 2);
            float mean = s * (1.0f / 64.0f);
            float var = sq * (1.0f / 64.0f) - mean * mean;
            float istd = rsqrtf(var + GN_EPS);
            size_t grow = (size_t)(rowg0 + q0 + lrow);
#pragma unroll
            for (int df = 0; df < 8; df++) {
                int col = h * HDIM + df * 8 + 2 * t;
                float2 gw = *(const float2*)&gnw[col];
                float2 gb = *(const float2*)&gnb[col];
                float o0 = ((v[2 * df]     - mean) * istd * gw.x + gb.x) * osc;
                float o1 = ((v[2 * df + 1] - mean) * istd * gw.y + gb.y) * osc;
                __half h0 = __float2half_rn(o0);
                __half h1 = __float2half_rn(o1);
                __half2 ph; ph.x = h0; ph.y = h1;
                __half2 pl;
                pl.x = __float2half_rn(o0 - __half2float(h0));
                pl.y = __float2half_rn(o1 - __half2float(h1));
                *(__half2*)&OutH[grow * THD + col] = ph;
                *(__half2*)&OutL[grow * THD + col] = pl;
            }
        }
    }
}

// ---------------- kernel_launch ----------------
extern "C" void kernel_launch(void* const* d_in, const int* in_sizes, int n_in,
                              void* d_out, int out_size)
{
    const float* x   = (const float*)d_in[0];
    const float* Wq  = (const float*)d_in[1];
    const float* Wk  = (const float*)d_in[2];
    const float* Wv  = (const float*)d_in[3];
    const float* Wo  = (const float*)d_in[4];
    const float* lq1 = (const float*)d_in[5];
    const float* lk1 = (const float*)d_in[6];
    const float* lq2 = (const float*)d_in[7];
    const float* lk2 = (const float*)d_in[8];
    const float* lam = (const float*)d_in[9];
    const float* gnw = (const float*)d_in[10];
    const float* gnb = (const float*)d_in[11];
    float* out = (float*)d_out;

    float *cosT, *sinT;
    __half *Qh, *Kh, *V16, *xh, *xl, *Wq16, *Wk16, *Wv16, *Wo16, *Ah, *Al;
    cudaGetSymbolAddress((void**)&Qh, g_Qh);
    cudaGetSymbolAddress((void**)&Kh, g_Kh);
    cudaGetSymbolAddress((void**)&V16, g_V16);
    cudaGetSymbolAddress((void**)&cosT, g_cosT);
    cudaGetSymbolAddress((void**)&sinT, g_sinT);
    cudaGetSymbolAddress((void**)&xh, g_xh);
    cudaGetSymbolAddress((void**)&xl, g_xl);
    cudaGetSymbolAddress((void**)&Wq16, g_Wq16);
    cudaGetSymbolAddress((void**)&Wk16, g_Wk16);
    cudaGetSymbolAddress((void**)&Wv16, g_Wv16);
    cudaGetSymbolAddress((void**)&Wo16, g_Wo16);
    cudaGetSymbolAddress((void**)&Ah, g_Ah);
    cudaGetSymbolAddress((void**)&Al, g_Al);

    cudaFuncSetAttribute(attn_v10_kernel, cudaFuncAttributeMaxDynamicSharedMemorySize, ATT_SMEM);
    cudaFuncSetAttribute(gemm_qkv_kernel, cudaFuncAttributeMaxDynamicSharedMemorySize, GEMM_SMEM);
    cudaFuncSetAttribute(gemm_o_kernel, cudaFuncAttributeMaxDynamicSharedMemorySize, GEMM_SMEM);

    rope_tables_kernel<<<(SEQ * 32 + 255) / 256, 256>>>(cosT, sinT);
    prep_kernel<<<dim3((MROWS * DMODEL + 255) / 256, 5), 256>>>(
        x, Wq, Wk, Wv, Wo, xh, xl, Wq16, Wk16, Wv16, Wo16);

    gemm_qkv_kernel<<<dim3(40, MROWS / 128), 256, GEMM_SMEM>>>(
        xh, xl, Wq16, Wk16, Wv16, Qh, Kh, V16, cosT, sinT);

    attn_v10_kernel<<<dim3(SEQ / 64, BATCH * NHEAD), 256, ATT_SMEM>>>(
        Qh, Kh, V16, lq1, lk1, lq2, lk2, lam, gnw, gnb, Ah, Al);

    gemm_o_kernel<<<dim3(DMODEL / 128, MROWS / 128), 256, GEMM_SMEM>>>(
        Ah, Al, Wo16, out, MROWS, DMODEL, THD);
}